// round 7
// baseline (speedup 1.0000x reference)
#include <cuda_runtime.h>
#include <math.h>
#include <stdint.h>

// Problem constants
#define B_   8
#define P_   16384
#define M_   16
#define CI_  16
#define CO_  32
#define W_   17
#define WSLOT 18          // 17 conv w-slots + 1 residual slot
#define OSTRIDE 288       // floats per output row in Wf
#define WWS  20           // padded per-m stride for ww

typedef unsigned long long ull;

// packed f32x2 (SASS FFMA2) — only reachable via PTX
#define FMA_F32X2(d, a, b, c) \
    asm("fma.rn.f32x2 %0, %1, %2, %3;" : "=l"(d) : "l"(a), "l"(b), "l"(c))
#define PACK_REPL_F32X2(out, s) \
    asm("mov.b64 %0, {%1, %1};" : "=l"(out) : "r"(s))
#define UNPACK_F32X2(lo, hi, in) \
    asm("mov.b64 {%0, %1}, %2;" : "=r"(lo), "=r"(hi) : "l"(in))

// smem (floats): Wf [32][288] = 9216 ; per-warp (4): ww[16][20]+nb[16] = 336
// total = 9216 + 4*336 = 10560 floats = 42240 bytes ; 5 CTAs/SM = 211200 B

__global__ void __launch_bounds__(128, 5)
fused_conv_kernel(const float* __restrict__ in_pc,
                  const float* __restrict__ weights,
                  const float* __restrict__ bias,
                  const float* __restrict__ w_weights,
                  const float* __restrict__ weight_res,
                  const int*   __restrict__ neighbor_id,
                  float*       __restrict__ out)
{
    constexpr float SQ_CONV = 0.70710678118654752440f;
    constexpr float SQ_RES  = 0.70710678118654752440f;

    extern __shared__ float sm[];
    float* Wf = sm;                                   // [32][288]

    const int tid  = threadIdx.x;
    const int warp = tid >> 5;
    const int lane = tid & 31;

    float* ww_s = sm + 32 * OSTRIDE + warp * 336;     // [16][20]
    int*   nb_s = (int*)(ww_s + 320);                 // [16]

    // ---- stage weights: Wf[o][w*16+i], col 272.. holds weight_res ----
    for (int idx = tid; idx < W_ * 512; idx += 128) {
        int w   = idx >> 9;
        int rem = idx & 511;
        int o   = rem >> 4;
        int i   = rem & 15;
        Wf[o * OSTRIDE + w * 16 + i] = weights[idx];
    }
    for (int idx = tid; idx < 512; idx += 128) {
        int o = idx >> 4, i = idx & 15;
        Wf[o * OSTRIDE + 272 + i] = weight_res[idx];
    }

    const int p = blockIdx.x * 4 + warp;

    // ---- per-warp staging: neighbor ids, masked ww ----
    if (lane < 16) nb_s[lane] = neighbor_id[p * M_ + lane];
    __syncwarp();
    for (int idx = lane; idx < 272; idx += 32) {
        int m = idx / 17;
        int w = idx - m * 17;
        float v = w_weights[(size_t)p * 272 + idx];
        ww_s[m * WWS + w] = (nb_s[m] == P_) ? 0.0f : v;
    }
    __syncthreads();

    // lane ownership: bg = lane>>3 (0..3), ih = lane&7 (0..7)
    //   batches b_lo = bg, b_hi = bg+4 ; channel pair i = 2ih, 2ih+1.
    const int bg = lane >> 3;
    const int ih = lane & 7;
    const int b_lo = bg;
    const int b_hi = bg + 4;

    // gacc2[w]: f32x2 packed over the channel pair (per b-slot). slot 17 = own x.
    ull gacc2[WSLOT][2];
    #pragma unroll
    for (int w = 0; w < 17; w++) { gacc2[w][0] = 0ull; gacc2[w][1] = 0ull; }
    {
        gacc2[17][0] = *(const ull*)&in_pc[((size_t)b_lo * P_ + p) * CI_ + 2 * ih];
        gacc2[17][1] = *(const ull*)&in_pc[((size_t)b_hi * P_ + p) * CI_ + 2 * ih];
    }

    // ---- stage A: packed over channels ----
    const float* xlo = in_pc + (size_t)b_lo * P_ * CI_ + 2 * ih;
    const float* xhi = in_pc + (size_t)b_hi * P_ * CI_ + 2 * ih;
    #pragma unroll 4
    for (int m = 0; m < M_; m++) {
        int nb  = nb_s[m];
        int nbc = (nb == P_) ? 0 : nb;          // ww zeroed for pad
        ull xa = *(const ull*)(xlo + (size_t)nbc * CI_);
        ull xc = *(const ull*)(xhi + (size_t)nbc * CI_);
        const float* wwm = ww_s + m * WWS;
        #pragma unroll
        for (int wg = 0; wg < 4; wg++) {
            float4 wv = *(const float4*)(wwm + wg * 4);
            int w = wg * 4;
            ull f2;
            uint32_t fb;
            fb = __float_as_uint(wv.x); PACK_REPL_F32X2(f2, fb);
            FMA_F32X2(gacc2[w+0][0], f2, xa, gacc2[w+0][0]);
            FMA_F32X2(gacc2[w+0][1], f2, xc, gacc2[w+0][1]);
            fb = __float_as_uint(wv.y); PACK_REPL_F32X2(f2, fb);
            FMA_F32X2(gacc2[w+1][0], f2, xa, gacc2[w+1][0]);
            FMA_F32X2(gacc2[w+1][1], f2, xc, gacc2[w+1][1]);
            fb = __float_as_uint(wv.z); PACK_REPL_F32X2(f2, fb);
            FMA_F32X2(gacc2[w+2][0], f2, xa, gacc2[w+2][0]);
            FMA_F32X2(gacc2[w+2][1], f2, xc, gacc2[w+2][1]);
            fb = __float_as_uint(wv.w); PACK_REPL_F32X2(f2, fb);
            FMA_F32X2(gacc2[w+3][0], f2, xa, gacc2[w+3][0]);
            FMA_F32X2(gacc2[w+3][1], f2, xc, gacc2[w+3][1]);
        }
        {
            uint32_t fb = __float_as_uint(wwm[16]);
            ull f2; PACK_REPL_F32X2(f2, fb);
            FMA_F32X2(gacc2[16][0], f2, xa, gacc2[16][0]);
            FMA_F32X2(gacc2[16][1], f2, xc, gacc2[16][1]);
        }
    }

    // unpack own-x (residual input) once
    float g17l0, g17l1, g17h0, g17h1;
    {
        uint32_t a0u, a1u;
        UNPACK_F32X2(a0u, a1u, gacc2[17][0]);
        g17l0 = __uint_as_float(a0u); g17l1 = __uint_as_float(a1u);
        UNPACK_F32X2(a0u, a1u, gacc2[17][1]);
        g17h0 = __uint_as_float(a0u); g17h1 = __uint_as_float(a1u);
    }

    // ---- stage B: o-blocks of 4, packed FFMA2 on Wf LDS.64 ----
    const float* wfih = Wf + 2 * ih;
    const bool h4 = (ih & 4) != 0;
    const bool h2 = (ih & 2) != 0;
    const bool h1 = (ih & 1) != 0;
    // final ownership (per og): oo = (ih>>1)&3, j = ih&1
    const int oo_fin = (ih >> 1) & 3;
    const int b_fin  = h1 ? b_hi : b_lo;
    float* outb = out + ((size_t)b_fin * P_ + p) * CO_;
    const float* biasp = bias + (size_t)p * CO_;

    #pragma unroll 1
    for (int og = 0; og < 8; og++) {
        const float* wfo = wfih + og * 4 * OSTRIDE;

        ull acc2[4][2];
        #pragma unroll
        for (int oo = 0; oo < 4; oo++) { acc2[oo][0] = 0ull; acc2[oo][1] = 0ull; }

        #pragma unroll
        for (int w = 0; w < 17; w++) {
            #pragma unroll
            for (int oo = 0; oo < 4; oo++) {
                ull wv = *(const ull*)(wfo + oo * OSTRIDE + w * 16);
                FMA_F32X2(acc2[oo][0], wv, gacc2[w][0], acc2[oo][0]);
                FMA_F32X2(acc2[oo][1], wv, gacc2[w][1], acc2[oo][1]);
            }
        }

        // horizontal add (channel pair) -> scalar partials ; residual partials
        float av[4][2], rv[4][2];
        #pragma unroll
        for (int oo = 0; oo < 4; oo++) {
            uint32_t l0, hi0, l1, hi1;
            UNPACK_F32X2(l0, hi0, acc2[oo][0]);
            UNPACK_F32X2(l1, hi1, acc2[oo][1]);
            av[oo][0] = __uint_as_float(l0) + __uint_as_float(hi0);
            av[oo][1] = __uint_as_float(l1) + __uint_as_float(hi1);
            float2 wr = *(const float2*)(wfo + oo * OSTRIDE + 272);
            rv[oo][0] = wr.x * g17l0 + wr.y * g17l1;
            rv[oo][1] = wr.x * g17h0 + wr.y * g17h1;
        }

        // ---- reduce-scatter over 8 ih lanes: (oo1,oo0,j) <- (bit2,bit1,bit0)
        float a2[2][2], r2[2][2];
        #pragma unroll
        for (int t = 0; t < 2; t++) {
            #pragma unroll
            for (int j = 0; j < 2; j++) {
                float ka = h4 ? av[2+t][j] : av[t][j];
                float sa = h4 ? av[t][j]   : av[2+t][j];
                a2[t][j] = ka + __shfl_xor_sync(0xffffffffu, sa, 4);
                float kr = h4 ? rv[2+t][j] : rv[t][j];
                float sr = h4 ? rv[t][j]   : rv[2+t][j];
                r2[t][j] = kr + __shfl_xor_sync(0xffffffffu, sr, 4);
            }
        }
        float a1[2], r1[2];
        #pragma unroll
        for (int j = 0; j < 2; j++) {
            float ka = h2 ? a2[1][j] : a2[0][j];
            float sa = h2 ? a2[0][j] : a2[1][j];
            a1[j] = ka + __shfl_xor_sync(0xffffffffu, sa, 2);
            float kr = h2 ? r2[1][j] : r2[0][j];
            float sr = h2 ? r2[0][j] : r2[1][j];
            r1[j] = kr + __shfl_xor_sync(0xffffffffu, sr, 2);
        }
        float a0, r0;
        {
            float ka = h1 ? a1[1] : a1[0];
            float sa = h1 ? a1[0] : a1[1];
            a0 = ka + __shfl_xor_sync(0xffffffffu, sa, 1);
            float kr = h1 ? r1[1] : r1[0];
            float sr = h1 ? r1[0] : r1[1];
            r0 = kr + __shfl_xor_sync(0xffffffffu, sr, 1);
        }

        // ---- epilogue: every lane owns (o = og*4 + oo_fin, b = b_fin) ----
        const int o = og * 4 + oo_fin;
        float c = a0 + biasp[o];
        float e = (c > 0.0f) ? c : expm1f(c);
        outb[o] = e * SQ_CONV + r0 * SQ_RES;
    }
}

extern "C" void kernel_launch(void* const* d_in, const int* in_sizes, int n_in,
                              void* d_out, int out_size)
{
    const float* in_pc       = nullptr;
    const float* weights     = nullptr;
    const float* bias        = nullptr;
    const float* w_weights   = nullptr;
    const float* weight_res  = nullptr;
    const int*   neighbor_id = nullptr;

    for (int i = 0; i < n_in; i++) {
        switch (in_sizes[i]) {
            case 2097152: in_pc       = (const float*)d_in[i]; break; // (8,16384,16)
            case 8704:    weights     = (const float*)d_in[i]; break; // (17,512)
            case 524288:  bias        = (const float*)d_in[i]; break; // (16384,32)
            case 4456448: w_weights   = (const float*)d_in[i]; break; // (16384,16,17)
            case 512:     weight_res  = (const float*)d_in[i]; break; // (32,16)
            case 262144:  neighbor_id = (const int*)d_in[i];   break; // (16384,16)
            default: break;
        }
    }

    const int smem_bytes = 10560 * 4; // 42240
    cudaFuncSetAttribute(fused_conv_kernel,
                         cudaFuncAttributeMaxDynamicSharedMemorySize, smem_bytes);

    fused_conv_kernel<<<P_ / 4, 128, smem_bytes>>>(
        in_pc, weights, bias, w_weights, weight_res, neighbor_id, (float*)d_out);
}

// round 8
// speedup vs baseline: 1.1878x; 1.1878x over previous
#include <cuda_runtime.h>
#include <math.h>
#include <stdint.h>

// Problem constants
#define B_   8
#define P_   16384
#define M_   16
#define CI_  16
#define CO_  32
#define W_   17
#define WSLOT 18          // 17 conv w-slots + 1 residual slot
#define OSTRIDE 288       // floats per output row in Wf

typedef unsigned long long ull;

// packed f32x2 (SASS FFMA2) — only reachable via PTX
#define FMA_F32X2(d, a, b, c) \
    asm("fma.rn.f32x2 %0, %1, %2, %3;" : "=l"(d) : "l"(a), "l"(b), "l"(c))
#define PACK_REPL_F32X2(out, s) \
    asm("mov.b64 %0, {%1, %1};" : "=l"(out) : "r"(s))
#define UNPACK_F32X2(lo, hi, in) \
    asm("mov.b64 {%0, %1}, %2;" : "=r"(lo), "=r"(hi) : "l"(in))

// smem (floats): Wf [32][288] = 9216 ; per-warp (4): nb[16] ints
// total = 9216 + 64 = 9280 floats = 37120 bytes

__global__ void __launch_bounds__(128, 4)
fused_conv_kernel(const float* __restrict__ in_pc,
                  const float* __restrict__ weights,
                  const float* __restrict__ bias,
                  const float* __restrict__ w_weights,
                  const float* __restrict__ weight_res,
                  const int*   __restrict__ neighbor_id,
                  float*       __restrict__ out)
{
    constexpr float SQ_CONV = 0.70710678118654752440f;
    constexpr float SQ_RES  = 0.70710678118654752440f;

    extern __shared__ float sm[];
    float* Wf = sm;                                   // [32][288]

    const int tid  = threadIdx.x;
    const int warp = tid >> 5;
    const int lane = tid & 31;

    int* nb_s = (int*)(sm + 32 * OSTRIDE) + warp * 16; // [16]

    // ---- stage weights: Wf[o][w*16+i], col 272.. holds weight_res ----
    for (int idx = tid; idx < W_ * 512; idx += 128) {
        int w   = idx >> 9;
        int rem = idx & 511;
        int o   = rem >> 4;
        int i   = rem & 15;
        Wf[o * OSTRIDE + w * 16 + i] = weights[idx];
    }
    for (int idx = tid; idx < 512; idx += 128) {
        int o = idx >> 4, i = idx & 15;
        Wf[o * OSTRIDE + 272 + i] = weight_res[idx];
    }

    const int p = blockIdx.x * 4 + warp;

    // ---- per-warp staging: neighbor ids to smem; ww to REGISTERS ----
    if (lane < 16) nb_s[lane] = neighbor_id[p * M_ + lane];
    __syncwarp();

    // lane (m2 = lane>>1, half = lane&1) owns ww slots:
    //   half0: w = 0..8 (9 values) ; half1: w = 9..16 (8 values, [8] = 0)
    float wwreg[9];
    {
        const int m2   = lane >> 1;
        const int half = lane & 1;
        const float* wsrc = w_weights + (size_t)p * 272 + m2 * 17 + half * 9;
        const bool dead = (nb_s[m2] == P_);
        #pragma unroll
        for (int s = 0; s < 8; s++) wwreg[s] = dead ? 0.0f : wsrc[s];
        wwreg[8] = (dead || half) ? 0.0f : wsrc[8];
    }
    __syncthreads();   // Wf visible

    // lane ownership: bg = lane>>3 (0..3), ih = lane&7 (0..7)
    //   batches b_lo = bg, b_hi = bg+4 ; channel pair i = 2ih, 2ih+1.
    const int bg = lane >> 3;
    const int ih = lane & 7;
    const int b_lo = bg;
    const int b_hi = bg + 4;

    // gacc2[w]: f32x2 packed over the channel pair (per b-slot). slot 17 = own x.
    ull gacc2[WSLOT][2];
    #pragma unroll
    for (int w = 0; w < 17; w++) { gacc2[w][0] = 0ull; gacc2[w][1] = 0ull; }
    {
        gacc2[17][0] = *(const ull*)&in_pc[((size_t)b_lo * P_ + p) * CI_ + 2 * ih];
        gacc2[17][1] = *(const ull*)&in_pc[((size_t)b_hi * P_ + p) * CI_ + 2 * ih];
    }

    // ---- stage A: ww via shfl broadcast, packed FFMA2 over channels ----
    const float* xlo = in_pc + (size_t)b_lo * P_ * CI_ + 2 * ih;
    const float* xhi = in_pc + (size_t)b_hi * P_ * CI_ + 2 * ih;
    #pragma unroll 4
    for (int m = 0; m < M_; m++) {
        int nb  = nb_s[m];
        int nbc = (nb == P_) ? 0 : nb;          // wwreg zeroed for pad
        ull xa = *(const ull*)(xlo + (size_t)nbc * CI_);
        ull xc = *(const ull*)(xhi + (size_t)nbc * CI_);
        const int src0 = 2 * m;
        #pragma unroll
        for (int s = 0; s < 17; s++) {
            const int ri  = (s >= 9) ? (s - 9) : s;
            const int src = (s >= 9) ? (src0 + 1) : src0;
            float f = __shfl_sync(0xffffffffu, wwreg[ri], src);
            ull f2;
            uint32_t fb = __float_as_uint(f);
            PACK_REPL_F32X2(f2, fb);
            FMA_F32X2(gacc2[s][0], f2, xa, gacc2[s][0]);
            FMA_F32X2(gacc2[s][1], f2, xc, gacc2[s][1]);
        }
    }

    // unpack own-x (residual input) once
    float g17l0, g17l1, g17h0, g17h1;
    {
        uint32_t a0u, a1u;
        UNPACK_F32X2(a0u, a1u, gacc2[17][0]);
        g17l0 = __uint_as_float(a0u); g17l1 = __uint_as_float(a1u);
        UNPACK_F32X2(a0u, a1u, gacc2[17][1]);
        g17h0 = __uint_as_float(a0u); g17h1 = __uint_as_float(a1u);
    }

    // ---- stage B: packed FFMA2 on Wf LDS.64 (register-pair = packed operand) ----
    const float* wfih = Wf + 2 * ih;

    #pragma unroll 1
    for (int og = 0; og < 4; og++) {
        const float* wfo = wfih + og * 8 * OSTRIDE;

        ull acc2[8][2];
        #pragma unroll
        for (int oo = 0; oo < 8; oo++) { acc2[oo][0] = 0ull; acc2[oo][1] = 0ull; }

        #pragma unroll
        for (int w = 0; w < 17; w++) {
            #pragma unroll
            for (int oo = 0; oo < 8; oo++) {
                ull wv = *(const ull*)(wfo + oo * OSTRIDE + w * 16);
                FMA_F32X2(acc2[oo][0], wv, gacc2[w][0], acc2[oo][0]);
                FMA_F32X2(acc2[oo][1], wv, gacc2[w][1], acc2[oo][1]);
            }
        }

        // horizontal add (channel pair) -> scalar partials
        float acc[8][2];
        #pragma unroll
        for (int oo = 0; oo < 8; oo++) {
            uint32_t l0, h0, l1, h1;
            UNPACK_F32X2(l0, h0, acc2[oo][0]);
            UNPACK_F32X2(l1, h1, acc2[oo][1]);
            acc[oo][0] = __uint_as_float(l0) + __uint_as_float(h0);
            acc[oo][1] = __uint_as_float(l1) + __uint_as_float(h1);
        }

        // residual partials (scalar; w-slot 17)
        float racc[8][2];
        #pragma unroll
        for (int oo = 0; oo < 8; oo++) {
            float2 wv = *(const float2*)(wfo + oo * OSTRIDE + 272);
            racc[oo][0] = wv.x * g17l0 + wv.y * g17l1;
            racc[oo][1] = wv.x * g17h0 + wv.y * g17h1;
        }

        // ---- reduce-scatter over the 8 ih lanes: lane ends with oo = ih ----
        float a2[4][2], r2[4][2];
        {
            const bool h = (ih & 4) != 0;
            #pragma unroll
            for (int t = 0; t < 4; t++) {
                #pragma unroll
                for (int j = 0; j < 2; j++) {
                    float ka = h ? acc[4+t][j]  : acc[t][j];
                    float sa = h ? acc[t][j]    : acc[4+t][j];
                    a2[t][j] = ka + __shfl_xor_sync(0xffffffffu, sa, 4);
                    float kr = h ? racc[4+t][j] : racc[t][j];
                    float sr = h ? racc[t][j]   : racc[4+t][j];
                    r2[t][j] = kr + __shfl_xor_sync(0xffffffffu, sr, 4);
                }
            }
        }
        float a1[2][2], r1[2][2];
        {
            const bool h = (ih & 2) != 0;
            #pragma unroll
            for (int t = 0; t < 2; t++) {
                #pragma unroll
                for (int j = 0; j < 2; j++) {
                    float ka = h ? a2[2+t][j] : a2[t][j];
                    float sa = h ? a2[t][j]   : a2[2+t][j];
                    a1[t][j] = ka + __shfl_xor_sync(0xffffffffu, sa, 2);
                    float kr = h ? r2[2+t][j] : r2[t][j];
                    float sr = h ? r2[t][j]   : r2[2+t][j];
                    r1[t][j] = kr + __shfl_xor_sync(0xffffffffu, sr, 2);
                }
            }
        }
        float a0[2], r0[2];
        {
            const bool h = (ih & 1) != 0;
            #pragma unroll
            for (int j = 0; j < 2; j++) {
                float ka = h ? a1[1][j] : a1[0][j];
                float sa = h ? a1[0][j] : a1[1][j];
                a0[j] = ka + __shfl_xor_sync(0xffffffffu, sa, 1);
                float kr = h ? r1[1][j] : r1[0][j];
                float sr = h ? r1[0][j] : r1[1][j];
                r0[j] = kr + __shfl_xor_sync(0xffffffffu, sr, 1);
            }
        }

        // ---- epilogue: lane writes o = og*8 + ih for its two batches ----
        const int o = og * 8 + ih;
        float bi = bias[(size_t)p * CO_ + o];

        float c0 = a0[0] + bi;
        float e0 = (c0 > 0.0f) ? c0 : expm1f(c0);
        out[((size_t)b_lo * P_ + p) * CO_ + o] = e0 * SQ_CONV + r0[0] * SQ_RES;

        float c1 = a0[1] + bi;
        float e1 = (c1 > 0.0f) ? c1 : expm1f(c1);
        out[((size_t)b_hi * P_ + p) * CO_ + o] = e1 * SQ_CONV + r0[1] * SQ_RES;
    }
}

extern "C" void kernel_launch(void* const* d_in, const int* in_sizes, int n_in,
                              void* d_out, int out_size)
{
    const float* in_pc       = nullptr;
    const float* weights     = nullptr;
    const float* bias        = nullptr;
    const float* w_weights   = nullptr;
    const float* weight_res  = nullptr;
    const int*   neighbor_id = nullptr;

    for (int i = 0; i < n_in; i++) {
        switch (in_sizes[i]) {
            case 2097152: in_pc       = (const float*)d_in[i]; break; // (8,16384,16)
            case 8704:    weights     = (const float*)d_in[i]; break; // (17,512)
            case 524288:  bias        = (const float*)d_in[i]; break; // (16384,32)
            case 4456448: w_weights   = (const float*)d_in[i]; break; // (16384,16,17)
            case 512:     weight_res  = (const float*)d_in[i]; break; // (32,16)
            case 262144:  neighbor_id = (const int*)d_in[i];   break; // (16384,16)
            default: break;
        }
    }

    const int smem_bytes = 9280 * 4; // 37120
    cudaFuncSetAttribute(fused_conv_kernel,
                         cudaFuncAttributeMaxDynamicSharedMemorySize, smem_bytes);

    fused_conv_kernel<<<P_ / 4, 128, smem_bytes>>>(
        in_pc, weights, bias, w_weights, weight_res, neighbor_id, (float*)d_out);
}